// round 1
// baseline (speedup 1.0000x reference)
#include <cuda_runtime.h>
#include <math.h>

#define BATCH 512
#define DIMV  512
#define INSZ  1537
#define HV    1538

// ---------------- scratch (no allocations allowed) ----------------
__device__ float g_mlp_in[BATCH * INSZ];
__device__ float g_cosY[BATCH * DIMV];
__device__ float g_sinY[BATCH * DIMV];
__device__ float g_h0[BATCH * HV];
__device__ float g_h1[BATCH * HV];
__device__ float g_cf[BATCH * DIMV];
__device__ float g_fs[BATCH * DIMV];

// ---------------- prep: build mlp_in = [cos(yd), sin(yd), t-1, freqs] ----------------
__global__ void prep_kernel(const float* __restrict__ t, const float* __restrict__ y,
                            const float* __restrict__ freqs) {
    int b = blockIdx.x;
    float temb = t[0] - 1.0f;
    float* row = g_mlp_in + b * INSZ;
    for (int i = threadIdx.x; i < DIMV; i += blockDim.x) {
        float yv = y[b * (DIMV + 1) + i];
        float c = cosf(yv), s = sinf(yv);
        g_cosY[b * DIMV + i] = c;
        g_sinY[b * DIMV + i] = s;
        row[i] = c;
        row[DIMV + i] = s;
        row[2 * DIMV + 1 + i] = freqs[b * DIMV + i];
    }
    if (threadIdx.x == 0) row[2 * DIMV] = temb;
}

// ---------------- generic fused GEMM: C = act(A[M,K] @ B[K,N] + bias) ----------------
// 64x64 block tile, BK=16, 256 threads, 4x4 per thread.
template<int ACT>
__global__ __launch_bounds__(256)
void gemm_bias_act(const float* __restrict__ A, const float* __restrict__ B,
                   const float* __restrict__ bias, float* __restrict__ C,
                   int M, int N, int K) {
    __shared__ float As[16][64];   // [k][m]
    __shared__ float Bs[16][64];   // [k][n]

    int tid  = threadIdx.x;
    int m0   = blockIdx.y * 64;
    int n0   = blockIdx.x * 64;
    int trow = tid >> 4;           // 0..15
    int tcol = tid & 15;           // 0..15

    int a_row = tid >> 2;          // 0..63  (m within tile)
    int a_col = (tid & 3) * 4;     // k offset 0/4/8/12
    int b_row = tid >> 4;          // 0..15  (k within tile)
    int b_col = (tid & 15) * 4;    // n offset

    float acc[4][4] = {};

    for (int k0 = 0; k0 < K; k0 += 16) {
        // A tile (transposed into [k][m])
        #pragma unroll
        for (int i = 0; i < 4; i++) {
            int kk = k0 + a_col + i;
            int m  = m0 + a_row;
            float v = 0.f;
            if (kk < K && m < M) v = A[m * K + kk];
            As[a_col + i][a_row] = v;
        }
        // B tile (natural [k][n])
        #pragma unroll
        for (int i = 0; i < 4; i++) {
            int kk = k0 + b_row;
            int n  = n0 + b_col + i;
            float v = 0.f;
            if (kk < K && n < N) v = B[kk * N + n];
            Bs[b_row][b_col + i] = v;
        }
        __syncthreads();

        #pragma unroll
        for (int kk = 0; kk < 16; kk++) {
            float4 av = *reinterpret_cast<const float4*>(&As[kk][trow * 4]);
            float4 bv = *reinterpret_cast<const float4*>(&Bs[kk][tcol * 4]);
            float a[4] = {av.x, av.y, av.z, av.w};
            float b[4] = {bv.x, bv.y, bv.z, bv.w};
            #pragma unroll
            for (int i = 0; i < 4; i++)
                #pragma unroll
                for (int j = 0; j < 4; j++)
                    acc[i][j] += a[i] * b[j];
        }
        __syncthreads();
    }

    #pragma unroll
    for (int i = 0; i < 4; i++) {
        int m = m0 + trow * 4 + i;
        if (m >= M) continue;
        #pragma unroll
        for (int j = 0; j < 4; j++) {
            int n = n0 + tcol * 4 + j;
            if (n < N) {
                float v = acc[i][j] + bias[n];
                if (ACT) v = tanhf(v);
                C[m * N + n] = v;
            }
        }
    }
}

// ---------------- forcesum: C ⊙ (S@Aᵀ) − S ⊙ (C@Aᵀ), dual-accumulator NT GEMM ----------------
__global__ __launch_bounds__(256)
void forcesum_kernel(const float* __restrict__ Amat) {
    __shared__ float Ss[16][64];   // [k][b]
    __shared__ float Cs[16][64];   // [k][b]
    __shared__ float At[16][64];   // [k][i]

    int tid  = threadIdx.x;
    int m0   = blockIdx.y * 64;    // batch
    int n0   = blockIdx.x * 64;    // oscillator index i
    int trow = tid >> 4;
    int tcol = tid & 15;

    int l_row = tid >> 2;          // 0..63
    int l_col = (tid & 3) * 4;     // k offset

    float acc_s[4][4] = {};
    float acc_c[4][4] = {};

    for (int k0 = 0; k0 < DIMV; k0 += 16) {
        #pragma unroll
        for (int i = 0; i < 4; i++) {
            int kk = k0 + l_col + i;
            Ss[l_col + i][l_row] = g_sinY[(m0 + l_row) * DIMV + kk];
            Cs[l_col + i][l_row] = g_cosY[(m0 + l_row) * DIMV + kk];
            At[l_col + i][l_row] = Amat[(n0 + l_row) * DIMV + kk];
        }
        __syncthreads();

        #pragma unroll
        for (int kk = 0; kk < 16; kk++) {
            float4 sv = *reinterpret_cast<const float4*>(&Ss[kk][trow * 4]);
            float4 cv = *reinterpret_cast<const float4*>(&Cs[kk][trow * 4]);
            float4 av = *reinterpret_cast<const float4*>(&At[kk][tcol * 4]);
            float s[4] = {sv.x, sv.y, sv.z, sv.w};
            float c[4] = {cv.x, cv.y, cv.z, cv.w};
            float a[4] = {av.x, av.y, av.z, av.w};
            #pragma unroll
            for (int i = 0; i < 4; i++)
                #pragma unroll
                for (int j = 0; j < 4; j++) {
                    acc_s[i][j] += s[i] * a[j];
                    acc_c[i][j] += c[i] * a[j];
                }
        }
        __syncthreads();
    }

    #pragma unroll
    for (int i = 0; i < 4; i++) {
        int b = m0 + trow * 4 + i;
        #pragma unroll
        for (int j = 0; j < 4; j++) {
            int n = n0 + tcol * 4 + j;
            float cy = g_cosY[b * DIMV + n];
            float sy = g_sinY[b * DIMV + n];
            g_fs[b * DIMV + n] = cy * acc_s[i][j] - sy * acc_c[i][j];
        }
    }
}

// ---------------- final: force = cf*fs/dim + freqs ; f1 = rowsum(cf^2) ----------------
__global__ __launch_bounds__(256)
void final_kernel(const float* __restrict__ freqs, float* __restrict__ out) {
    int b   = blockIdx.x;
    int tid = threadIdx.x;
    float sum = 0.f;
    for (int i = tid; i < DIMV; i += 256) {
        float cf = g_cf[b * DIMV + i];
        float fv = cf * g_fs[b * DIMV + i] * (1.0f / DIMV) + freqs[b * DIMV + i];
        out[b * (DIMV + 1) + i] = fv;
        sum += cf * cf;
    }
    __shared__ float red[8];
    #pragma unroll
    for (int o = 16; o; o >>= 1) sum += __shfl_down_sync(0xffffffffu, sum, o);
    if ((tid & 31) == 0) red[tid >> 5] = sum;
    __syncthreads();
    if (tid < 8) {
        float v = red[tid];
        #pragma unroll
        for (int o = 4; o; o >>= 1) v += __shfl_down_sync(0xffu, v, o);
        if (tid == 0) out[b * (DIMV + 1) + DIMV] = v;
    }
}

// ---------------- launch ----------------
extern "C" void kernel_launch(void* const* d_in, const int* in_sizes, int n_in,
                              void* d_out, int out_size) {
    const float* t     = (const float*)d_in[0];
    const float* y     = (const float*)d_in[1];
    const float* freqs = (const float*)d_in[2];
    const float* A     = (const float*)d_in[3];
    const float* W0    = (const float*)d_in[4];
    const float* b0    = (const float*)d_in[5];
    const float* W1    = (const float*)d_in[6];
    const float* b1    = (const float*)d_in[7];
    const float* W2    = (const float*)d_in[8];
    const float* b2    = (const float*)d_in[9];
    const float* W3    = (const float*)d_in[10];
    const float* b3    = (const float*)d_in[11];
    float* out = (float*)d_out;

    float *p_in, *p_h0, *p_h1, *p_cf;
    cudaGetSymbolAddress((void**)&p_in, g_mlp_in);
    cudaGetSymbolAddress((void**)&p_h0, g_h0);
    cudaGetSymbolAddress((void**)&p_h1, g_h1);
    cudaGetSymbolAddress((void**)&p_cf, g_cf);

    prep_kernel<<<BATCH, 256>>>(t, y, freqs);

    dim3 gridH((HV + 63) / 64, BATCH / 64);     // (25, 8)
    dim3 gridD((DIMV + 63) / 64, BATCH / 64);   // (8, 8)

    gemm_bias_act<1><<<gridH, 256>>>(p_in, W0, b0, p_h0, BATCH, HV, INSZ);
    gemm_bias_act<1><<<gridH, 256>>>(p_h0, W1, b1, p_h1, BATCH, HV, HV);
    gemm_bias_act<1><<<gridH, 256>>>(p_h1, W2, b2, p_h0, BATCH, HV, HV);
    gemm_bias_act<0><<<gridD, 256>>>(p_h0, W3, b3, p_cf, BATCH, DIMV, HV);

    forcesum_kernel<<<gridD, 256>>>(A);
    final_kernel<<<BATCH, 256>>>(freqs, out);
}

// round 3
// speedup vs baseline: 2.6986x; 2.6986x over previous
#include <cuda_runtime.h>
#include <cuda_bf16.h>
#include <math.h>
#include <stdint.h>

#define BATCH 512
#define DIMV  512
#define INSZ  1537
#define HV    1538
#define HP    1664   // padded h / in_sz (multiple of 128)

// ------------------------------------------------------------------
// scratch (__device__ globals; no allocations allowed)
// ------------------------------------------------------------------
__device__ __nv_bfloat16 g_a0h[BATCH * HP], g_a0l[BATCH * HP];
__device__ __nv_bfloat16 g_h0h[BATCH * HP], g_h0l[BATCH * HP];
__device__ __nv_bfloat16 g_h1h[BATCH * HP], g_h1l[BATCH * HP];
__device__ float g_cf[BATCH * DIMV];
__device__ float g_SC[2 * BATCH * DIMV];                    // fp32 [sin; cos]
__device__ __nv_bfloat16 g_SCh[2 * BATCH * DIMV], g_SCl[2 * BATCH * DIMV];
__device__ float g_FS[2 * BATCH * DIMV];
__device__ float g_zerobias[HP];                            // stays zero

__device__ __nv_bfloat16 g_W0h[HP * HP],   g_W0l[HP * HP];
__device__ __nv_bfloat16 g_W1h[HP * HP],   g_W1l[HP * HP];
__device__ __nv_bfloat16 g_W2h[HP * HP],   g_W2l[HP * HP];
__device__ __nv_bfloat16 g_W3h[DIMV * HP], g_W3l[DIMV * HP];
__device__ __nv_bfloat16 g_Ah[DIMV * DIMV], g_Al[DIMV * DIMV];

// ------------------------------------------------------------------
// helpers
// ------------------------------------------------------------------
__device__ __forceinline__ uint32_t smem_u32(const void* p) {
    uint32_t a;
    asm("{ .reg .u64 t; cvta.to.shared.u64 t, %1; cvt.u32.u64 %0, t; }"
        : "=r"(a) : "l"(p));
    return a;
}

#define CP_ASYNC16(dst, src) \
    asm volatile("cp.async.cg.shared.global [%0], [%1], 16;" \
                 :: "r"(dst), "l"(src) : "memory")
#define CP_COMMIT() asm volatile("cp.async.commit_group;" ::: "memory")
#define CP_WAIT1()  asm volatile("cp.async.wait_group 1;"  ::: "memory")

#define LDSM4(r, addr) \
    asm volatile("ldmatrix.sync.aligned.m8n8.x4.shared.b16 {%0,%1,%2,%3}, [%4];" \
                 : "=r"((r)[0]), "=r"((r)[1]), "=r"((r)[2]), "=r"((r)[3]) : "r"(addr))

#define MMA16816(d, a, b0, b1) \
    asm volatile("mma.sync.aligned.m16n8k16.row.col.f32.bf16.bf16.f32 " \
                 "{%0,%1,%2,%3}, {%4,%5,%6,%7}, {%8,%9}, {%0,%1,%2,%3};" \
                 : "+f"((d)[0]), "+f"((d)[1]), "+f"((d)[2]), "+f"((d)[3]) \
                 : "r"((a)[0]), "r"((a)[1]), "r"((a)[2]), "r"((a)[3]), \
                   "r"(b0), "r"(b1))

__device__ __forceinline__ void split_bf16(float x, unsigned short& h, unsigned short& l) {
    __nv_bfloat16 hb = __float2bfloat16(x);
    float r = x - __bfloat162float(hb);   // exact in fp32
    h = __bfloat16_as_ushort(hb);
    l = __bfloat16_as_ushort(__float2bfloat16(r));
}

// ------------------------------------------------------------------
// prep: a0 = split([cos, sin, t-1, freqs, 0pad]); SC = [sin; cos] (fp32 + split)
// ------------------------------------------------------------------
__global__ void prep_kernel(const float* __restrict__ t, const float* __restrict__ y,
                            const float* __restrict__ freqs) {
    int b = blockIdx.x, tid = threadIdx.x;
    float temb = t[0] - 1.0f;
    for (int i = tid; i < DIMV; i += 256) {
        float yv = y[b * (DIMV + 1) + i];
        float s, c;
        sincosf(yv, &s, &c);
        unsigned short ch, cl, sh, sl, fh, fl;
        split_bf16(c, ch, cl);
        split_bf16(s, sh, sl);
        float fq = freqs[b * DIMV + i];
        split_bf16(fq, fh, fl);
        size_t r = (size_t)b * HP;
        g_a0h[r + i] = __ushort_as_bfloat16(ch);
        g_a0l[r + i] = __ushort_as_bfloat16(cl);
        g_a0h[r + DIMV + i] = __ushort_as_bfloat16(sh);
        g_a0l[r + DIMV + i] = __ushort_as_bfloat16(sl);
        g_a0h[r + 2 * DIMV + 1 + i] = __ushort_as_bfloat16(fh);
        g_a0l[r + 2 * DIMV + 1 + i] = __ushort_as_bfloat16(fl);
        g_SC[b * DIMV + i] = s;
        g_SC[(BATCH + b) * DIMV + i] = c;
        unsigned short h2, l2;
        split_bf16(s, h2, l2);
        g_SCh[b * DIMV + i] = __ushort_as_bfloat16(h2);
        g_SCl[b * DIMV + i] = __ushort_as_bfloat16(l2);
        split_bf16(c, h2, l2);
        g_SCh[(BATCH + b) * DIMV + i] = __ushort_as_bfloat16(h2);
        g_SCl[(BATCH + b) * DIMV + i] = __ushort_as_bfloat16(l2);
    }
    if (tid == 0) {
        unsigned short th, tl;
        split_bf16(temb, th, tl);
        g_a0h[(size_t)b * HP + 2 * DIMV] = __ushort_as_bfloat16(th);
        g_a0l[(size_t)b * HP + 2 * DIMV] = __ushort_as_bfloat16(tl);
    }
    for (int i = INSZ + tid; i < HP; i += 256) {
        g_a0h[(size_t)b * HP + i] = __ushort_as_bfloat16(0);
        g_a0l[(size_t)b * HP + i] = __ushort_as_bfloat16(0);
    }
}

// ------------------------------------------------------------------
// weight transpose + split: dst[n][k] = split(src[k][n]); zero-padded
// ------------------------------------------------------------------
__global__ void transpose_convert(const float* __restrict__ src,
                                  __nv_bfloat16* __restrict__ dhi,
                                  __nv_bfloat16* __restrict__ dlo,
                                  int K, int N, int Kpad) {
    __shared__ float tile[32][33];
    int k0 = blockIdx.x * 32, n0 = blockIdx.y * 32;
    int tx = threadIdx.x, ty = threadIdx.y;
    #pragma unroll
    for (int i = 0; i < 4; i++) {
        int k = k0 + ty + i * 8, n = n0 + tx;
        tile[ty + i * 8][tx] = (k < K && n < N) ? src[(size_t)k * N + n] : 0.f;
    }
    __syncthreads();
    #pragma unroll
    for (int i = 0; i < 4; i++) {
        int n = n0 + ty + i * 8, k = k0 + tx;
        float v = tile[tx][ty + i * 8];
        unsigned short h, l;
        split_bf16(v, h, l);
        dhi[(size_t)n * Kpad + k] = __ushort_as_bfloat16(h);
        dlo[(size_t)n * Kpad + k] = __ushort_as_bfloat16(l);
    }
}

__global__ void convert_A(const float* __restrict__ A) {
    int i = blockIdx.x * 256 + threadIdx.x;
    float v = A[i];
    unsigned short h, l;
    split_bf16(v, h, l);
    g_Ah[i] = __ushort_as_bfloat16(h);
    g_Al[i] = __ushort_as_bfloat16(l);
}

// ------------------------------------------------------------------
// mma.sync GEMM: C[M,N] = act(A[M,K] @ B[N,K]^T + bias), split-precision bf16
// CTA 64x128, BK=32, 8 warps (2x4), warp tile 32x32, cp.async double buffer.
// Smem rows padded to 40 bf16 (80B) -> conflict-free ldmatrix.
// ------------------------------------------------------------------
#define ST_A  5120            // 64 rows * 80B
#define ST_B  10240           // 128 rows * 80B
#define STAGE 30720           // Ah + Al + Bh + Bl
#define SMEM_TOT (2 * STAGE)

template<int ACT, int OSPLIT>
__global__ __launch_bounds__(256)
void mma_gemm(const __nv_bfloat16* __restrict__ Ah, const __nv_bfloat16* __restrict__ Al, int lda,
              const __nv_bfloat16* __restrict__ Bh, const __nv_bfloat16* __restrict__ Bl, int ldb,
              const float* __restrict__ bias, int Nreal,
              float* __restrict__ Cf,
              __nv_bfloat16* __restrict__ Ch, __nv_bfloat16* __restrict__ Cl,
              int ldc, int K) {
    extern __shared__ __align__(16) char smraw[];
    uint32_t smbase = smem_u32(smraw);

    int tid = threadIdx.x;
    int wid = tid >> 5, lane = tid & 31;
    int wm = wid >> 2, wn = wid & 3;          // 2 x 4 warp grid
    int m0 = blockIdx.y * 64, n0 = blockIdx.x * 128;
    int Kc = K / 32;

    float acc[2][4][4];
    #pragma unroll
    for (int i = 0; i < 2; i++)
        #pragma unroll
        for (int j = 0; j < 4; j++)
            #pragma unroll
            for (int q = 0; q < 4; q++) acc[i][j][q] = 0.f;

    // per-thread load coordinates
    int arow = tid >> 2, ach = tid & 3;        // A: 64 rows x 4 chunks
    const __nv_bfloat16* pAh = Ah + (size_t)(m0 + arow) * lda + ach * 8;
    const __nv_bfloat16* pAl = Al + (size_t)(m0 + arow) * lda + ach * 8;

    auto load_stage = [&](int buf, int c) {
        uint32_t s = smbase + buf * STAGE;
        int k0 = c * 32;
        CP_ASYNC16(s + arow * 80 + ach * 16, pAh + k0);
        CP_ASYNC16(s + ST_A + arow * 80 + ach * 16, pAl + k0);
        #pragma unroll
        for (int i = 0; i < 2; i++) {
            int f = tid + i * 256;
            int brow = f >> 2, bch = f & 3;
            const __nv_bfloat16* pbh = Bh + (size_t)(n0 + brow) * ldb + k0 + bch * 8;
            const __nv_bfloat16* pbl = Bl + (size_t)(n0 + brow) * ldb + k0 + bch * 8;
            CP_ASYNC16(s + 2 * ST_A + brow * 80 + bch * 16, pbh);
            CP_ASYNC16(s + 2 * ST_A + ST_B + brow * 80 + bch * 16, pbl);
        }
    };

    load_stage(0, 0); CP_COMMIT();
    load_stage(1, 1); CP_COMMIT();

    // precomputed ldmatrix offsets (within a stage)
    int a_r = (lane & 15), a_c = (lane >> 4) << 3;
    int b_r = (lane & 7) + ((lane >> 4) << 3), b_c = ((lane >> 3) & 1) << 3;

    for (int c = 0; c < Kc; c++) {
        CP_WAIT1();
        __syncthreads();
        uint32_t s = smbase + (c & 1) * STAGE;
        uint32_t sAh = s, sAl = s + ST_A, sBh = s + 2 * ST_A, sBl = s + 2 * ST_A + ST_B;

        #pragma unroll
        for (int kk2 = 0; kk2 < 2; kk2++) {
            int kk = kk2 * 16;
            uint32_t ah[2][4], al[2][4], bh[2][4], bl[2][4];
            #pragma unroll
            for (int mi = 0; mi < 2; mi++) {
                uint32_t off = (uint32_t)((wm * 32 + mi * 16 + a_r) * 80 + (kk + a_c) * 2);
                LDSM4(ah[mi], sAh + off);
                LDSM4(al[mi], sAl + off);
            }
            #pragma unroll
            for (int ni = 0; ni < 2; ni++) {
                uint32_t off = (uint32_t)((wn * 32 + ni * 16 + b_r) * 80 + (kk + b_c) * 2);
                LDSM4(bh[ni], sBh + off);
                LDSM4(bl[ni], sBl + off);
            }
            #pragma unroll
            for (int mi = 0; mi < 2; mi++)
                #pragma unroll
                for (int nj = 0; nj < 4; nj++) {
                    uint32_t* Bhf = &bh[nj >> 1][(nj & 1) * 2];
                    uint32_t* Blf = &bl[nj >> 1][(nj & 1) * 2];
                    MMA16816(acc[mi][nj], ah[mi], Bhf[0], Bhf[1]);
                    MMA16816(acc[mi][nj], ah[mi], Blf[0], Blf[1]);
                    MMA16816(acc[mi][nj], al[mi], Bhf[0], Bhf[1]);
                }
        }
        __syncthreads();
        if (c + 2 < Kc) load_stage(c & 1, c + 2);
        CP_COMMIT();
    }

    // epilogue: bias + optional tanh, direct stores (fp32 or split bf16)
    #pragma unroll
    for (int mi = 0; mi < 2; mi++)
        #pragma unroll
        for (int nj = 0; nj < 4; nj++) {
            float* d = acc[mi][nj];
            int row = m0 + wm * 32 + mi * 16 + (lane >> 2);
            int col = n0 + wn * 32 + nj * 8 + (lane & 3) * 2;
            float bb0 = (col < Nreal) ? bias[col] : 0.f;
            float bb1 = (col + 1 < Nreal) ? bias[col + 1] : 0.f;
            float v0 = d[0] + bb0, v1 = d[1] + bb1;
            float v2 = d[2] + bb0, v3 = d[3] + bb1;
            if (ACT) { v0 = tanhf(v0); v1 = tanhf(v1); v2 = tanhf(v2); v3 = tanhf(v3); }
            if (OSPLIT) {
                unsigned short h0, l0, h1, l1;
                split_bf16(v0, h0, l0); split_bf16(v1, h1, l1);
                *(uint32_t*)((char*)Ch + ((size_t)row * ldc + col) * 2) = (uint32_t)h0 | ((uint32_t)h1 << 16);
                *(uint32_t*)((char*)Cl + ((size_t)row * ldc + col) * 2) = (uint32_t)l0 | ((uint32_t)l1 << 16);
                split_bf16(v2, h0, l0); split_bf16(v3, h1, l1);
                *(uint32_t*)((char*)Ch + ((size_t)(row + 8) * ldc + col) * 2) = (uint32_t)h0 | ((uint32_t)h1 << 16);
                *(uint32_t*)((char*)Cl + ((size_t)(row + 8) * ldc + col) * 2) = (uint32_t)l0 | ((uint32_t)l1 << 16);
            } else {
                float2 u0 = {v0, v1}, u1 = {v2, v3};
                *(float2*)(Cf + (size_t)row * ldc + col) = u0;
                *(float2*)(Cf + (size_t)(row + 8) * ldc + col) = u1;
            }
        }
}

// ------------------------------------------------------------------
// final: force = cf * (cos*FSs - sin*FSc) / dim + freqs ; f1 = rowsum(cf^2)
// ------------------------------------------------------------------
__global__ __launch_bounds__(256)
void final_kernel(const float* __restrict__ freqs, float* __restrict__ out) {
    int b = blockIdx.x, tid = threadIdx.x;
    float sum = 0.f;
    for (int i = tid; i < DIMV; i += 256) {
        float cf = g_cf[b * DIMV + i];
        float s = g_SC[b * DIMV + i];
        float c = g_SC[(BATCH + b) * DIMV + i];
        float fs = c * g_FS[b * DIMV + i] - s * g_FS[(BATCH + b) * DIMV + i];
        out[b * (DIMV + 1) + i] = cf * fs * (1.0f / DIMV) + freqs[b * DIMV + i];
        sum += cf * cf;
    }
    __shared__ float red[8];
    #pragma unroll
    for (int o = 16; o; o >>= 1) sum += __shfl_down_sync(0xffffffffu, sum, o);
    if ((tid & 31) == 0) red[tid >> 5] = sum;
    __syncthreads();
    if (tid < 8) {
        float v = red[tid];
        #pragma unroll
        for (int o = 4; o; o >>= 1) v += __shfl_down_sync(0xffu, v, o);
        if (tid == 0) out[b * (DIMV + 1) + DIMV] = v;
    }
}

// ------------------------------------------------------------------
// launch
// ------------------------------------------------------------------
extern "C" void kernel_launch(void* const* d_in, const int* in_sizes, int n_in,
                              void* d_out, int out_size) {
    const float* t     = (const float*)d_in[0];
    const float* y     = (const float*)d_in[1];
    const float* freqs = (const float*)d_in[2];
    const float* A     = (const float*)d_in[3];
    const float* W0    = (const float*)d_in[4];
    const float* b0    = (const float*)d_in[5];
    const float* W1    = (const float*)d_in[6];
    const float* b1    = (const float*)d_in[7];
    const float* W2    = (const float*)d_in[8];
    const float* b2    = (const float*)d_in[9];
    const float* W3    = (const float*)d_in[10];
    const float* b3    = (const float*)d_in[11];
    float* out = (float*)d_out;

    __nv_bfloat16 *p_a0h, *p_a0l, *p_h0h, *p_h0l, *p_h1h, *p_h1l;
    __nv_bfloat16 *p_SCh, *p_SCl;
    __nv_bfloat16 *p_W0h, *p_W0l, *p_W1h, *p_W1l, *p_W2h, *p_W2l, *p_W3h, *p_W3l, *p_Ah, *p_Al;
    float *p_cf, *p_FS, *p_zb;
    cudaGetSymbolAddress((void**)&p_a0h, g_a0h); cudaGetSymbolAddress((void**)&p_a0l, g_a0l);
    cudaGetSymbolAddress((void**)&p_h0h, g_h0h); cudaGetSymbolAddress((void**)&p_h0l, g_h0l);
    cudaGetSymbolAddress((void**)&p_h1h, g_h1h); cudaGetSymbolAddress((void**)&p_h1l, g_h1l);
    cudaGetSymbolAddress((void**)&p_SCh, g_SCh); cudaGetSymbolAddress((void**)&p_SCl, g_SCl);
    cudaGetSymbolAddress((void**)&p_cf, g_cf);
    cudaGetSymbolAddress((void**)&p_FS, g_FS);
    cudaGetSymbolAddress((void**)&p_zb, g_zerobias);
    cudaGetSymbolAddress((void**)&p_W0h, g_W0h); cudaGetSymbolAddress((void**)&p_W0l, g_W0l);
    cudaGetSymbolAddress((void**)&p_W1h, g_W1h); cudaGetSymbolAddress((void**)&p_W1l, g_W1l);
    cudaGetSymbolAddress((void**)&p_W2h, g_W2h); cudaGetSymbolAddress((void**)&p_W2l, g_W2l);
    cudaGetSymbolAddress((void**)&p_W3h, g_W3h); cudaGetSymbolAddress((void**)&p_W3l, g_W3l);
    cudaGetSymbolAddress((void**)&p_Ah, g_Ah);   cudaGetSymbolAddress((void**)&p_Al, g_Al);

    cudaFuncSetAttribute(mma_gemm<1,1>, cudaFuncAttributeMaxDynamicSharedMemorySize, SMEM_TOT);
    cudaFuncSetAttribute(mma_gemm<0,0>, cudaFuncAttributeMaxDynamicSharedMemorySize, SMEM_TOT);

    // prep + weight conversion
    prep_kernel<<<BATCH, 256>>>(t, y, freqs);
    dim3 tcb(32, 8);
    transpose_convert<<<dim3(HP / 32, HP / 32), tcb>>>(W0, p_W0h, p_W0l, INSZ, HV, HP);
    transpose_convert<<<dim3(HP / 32, HP / 32), tcb>>>(W1, p_W1h, p_W1l, HV, HV, HP);
    transpose_convert<<<dim3(HP / 32, HP / 32), tcb>>>(W2, p_W2h, p_W2l, HV, HV, HP);
    transpose_convert<<<dim3(HP / 32, DIMV / 32), tcb>>>(W3, p_W3h, p_W3l, HV, DIMV, HP);
    convert_A<<<(DIMV * DIMV) / 256, 256>>>(A);

    // forcesum: [sin;cos](1024x512) @ A^T -> FS (fp32)
    mma_gemm<0,0><<<dim3(DIMV / 128, (2 * BATCH) / 64), 256, SMEM_TOT>>>(
        p_SCh, p_SCl, DIMV, p_Ah, p_Al, DIMV, p_zb, DIMV,
        p_FS, nullptr, nullptr, DIMV, DIMV);

    // MLP chain (split outputs for hidden layers)
    dim3 gridH(HP / 128, BATCH / 64);     // (13, 8)
    dim3 gridD(DIMV / 128, BATCH / 64);   // (4, 8)
    mma_gemm<1,1><<<gridH, 256, SMEM_TOT>>>(p_a0h, p_a0l, HP, p_W0h, p_W0l, HP, b0, HV,
                                            nullptr, p_h0h, p_h0l, HP, HP);
    mma_gemm<1,1><<<gridH, 256, SMEM_TOT>>>(p_h0h, p_h0l, HP, p_W1h, p_W1l, HP, b1, HV,
                                            nullptr, p_h1h, p_h1l, HP, HP);
    mma_gemm<1,1><<<gridH, 256, SMEM_TOT>>>(p_h1h, p_h1l, HP, p_W2h, p_W2l, HP, b2, HV,
                                            nullptr, p_h0h, p_h0l, HP, HP);
    mma_gemm<0,0><<<gridD, 256, SMEM_TOT>>>(p_h0h, p_h0l, HP, p_W3h, p_W3l, HP, b3, DIMV,
                                            p_cf, nullptr, nullptr, DIMV, HP);

    final_kernel<<<BATCH, 256>>>(freqs, out);
}

// round 4
// speedup vs baseline: 4.0946x; 1.5173x over previous
#include <cuda_runtime.h>
#include <cuda_fp16.h>
#include <math.h>
#include <stdint.h>

#define BATCH 512
#define DIMV  512
#define INSZ  1537
#define HV    1538
#define HP    1664          // padded h / in_sz (multiple of 128)

// GEMM tiling
#define BM 64
#define BN 128
#define BK 32
#define NS 3                // cp.async stages
#define ST_A (64 * 80)      // 5120  : 64 rows x (32 fp16 = 64B, padded 80B)
#define ST_B (128 * 80)     // 10240
#define STG  (ST_A + 2 * ST_B)   // 25600 : A | Bh | Bl
#define SMEM_TOT (NS * STG)      // 76800

// ------------------------------------------------------------------
// scratch (__device__ globals; no allocations allowed)
// ------------------------------------------------------------------
__device__ __half g_a0[BATCH * HP];
__device__ __half g_hA[BATCH * HP];
__device__ __half g_hB[BATCH * HP];
__device__ __half g_SCh[2 * BATCH * DIMV];     // fp16 [sin; cos]
__device__ float  g_SC[2 * BATCH * DIMV];      // fp32 [sin; cos]
__device__ float  g_FS[2 * BATCH * DIMV];      // forcesum partial GEMMs
__device__ float  g_part[4 * BATCH * DIMV];    // L3 split-K partials

__device__ __half g_W0h[HP * HP],   g_W0l[HP * HP];
__device__ __half g_W1h[HP * HP],   g_W1l[HP * HP];
__device__ __half g_W2h[HP * HP],   g_W2l[HP * HP];
__device__ __half g_W3h[DIMV * HP], g_W3l[DIMV * HP];
__device__ __half g_Ah[DIMV * DIMV], g_Al[DIMV * DIMV];

// ------------------------------------------------------------------
// helpers
// ------------------------------------------------------------------
__device__ __forceinline__ uint32_t smem_u32(const void* p) {
    uint32_t a;
    asm("{ .reg .u64 t; cvta.to.shared.u64 t, %1; cvt.u32.u64 %0, t; }"
        : "=r"(a) : "l"(p));
    return a;
}

#define CP_ASYNC16(dst, src) \
    asm volatile("cp.async.cg.shared.global [%0], [%1], 16;" \
                 :: "r"(dst), "l"(src) : "memory")
#define CP_COMMIT() asm volatile("cp.async.commit_group;" ::: "memory")
#define CP_WAIT2()  asm volatile("cp.async.wait_group 2;"  ::: "memory")

#define LDSM4(r, addr) \
    asm volatile("ldmatrix.sync.aligned.m8n8.x4.shared.b16 {%0,%1,%2,%3}, [%4];" \
                 : "=r"((r)[0]), "=r"((r)[1]), "=r"((r)[2]), "=r"((r)[3]) : "r"(addr))

#define MMA16816(d, a, b0, b1) \
    asm volatile("mma.sync.aligned.m16n8k16.row.col.f32.f16.f16.f32 " \
                 "{%0,%1,%2,%3}, {%4,%5,%6,%7}, {%8,%9}, {%0,%1,%2,%3};" \
                 : "+f"((d)[0]), "+f"((d)[1]), "+f"((d)[2]), "+f"((d)[3]) \
                 : "r"((a)[0]), "r"((a)[1]), "r"((a)[2]), "r"((a)[3]), \
                   "r"(b0), "r"(b1))

__device__ __forceinline__ void split_h(float x, unsigned short& h, unsigned short& l) {
    __half hh = __float2half_rn(x);
    float r = x - __half2float(hh);
    h = __half_as_ushort(hh);
    l = __half_as_ushort(__float2half_rn(r));
}
__device__ __forceinline__ unsigned short h_bits(float x) {
    return __half_as_ushort(__float2half_rn(x));
}

// ------------------------------------------------------------------
// prep: a0 = fp16[cos, sin, t-1, freqs, 0pad]; SC fp16+fp32 [sin; cos]
// ------------------------------------------------------------------
__global__ void prep_kernel(const float* __restrict__ t, const float* __restrict__ y,
                            const float* __restrict__ freqs) {
    int b = blockIdx.x, tid = threadIdx.x;
    float temb = t[0] - 1.0f;
    __half* row = g_a0 + (size_t)b * HP;
    for (int i = tid; i < DIMV; i += 256) {
        float yv = y[b * (DIMV + 1) + i];
        float s, c;
        sincosf(yv, &s, &c);
        float fq = freqs[b * DIMV + i];
        row[i] = __float2half_rn(c);
        row[DIMV + i] = __float2half_rn(s);
        row[2 * DIMV + 1 + i] = __float2half_rn(fq);
        g_SC[b * DIMV + i] = s;
        g_SC[(BATCH + b) * DIMV + i] = c;
        g_SCh[b * DIMV + i] = __float2half_rn(s);
        g_SCh[(BATCH + b) * DIMV + i] = __float2half_rn(c);
    }
    if (tid == 0) row[2 * DIMV] = __float2half_rn(temb);
    for (int i = INSZ + tid; i < HP; i += 256) row[i] = __ushort_as_half(0);
}

// ------------------------------------------------------------------
// fused conversion: W0..W3 transpose+split (64x64 tiles) + A split
// block dispatch: [0,676) W0 | [676,1352) W1 | [1352,2028) W2 |
//                 [2028,2236) W3 | [2236,2492) A elementwise
// ------------------------------------------------------------------
__global__ __launch_bounds__(256)
void convert_all(const float* __restrict__ W0, const float* __restrict__ W1,
                 const float* __restrict__ W2, const float* __restrict__ W3,
                 const float* __restrict__ A) {
    int bid = blockIdx.x, tid = threadIdx.x;

    if (bid >= 2236) {               // A: elementwise split, float4 vectorized
        int idx4 = (bid - 2236) * 256 + tid;          // 256 blocks * 256 thr * 4 el
        float4 v = reinterpret_cast<const float4*>(A)[idx4];
        unsigned short h0, l0, h1, l1, h2, l2, h3, l3;
        split_h(v.x, h0, l0); split_h(v.y, h1, l1);
        split_h(v.z, h2, l2); split_h(v.w, h3, l3);
        uint2 hw = {(uint32_t)h0 | ((uint32_t)h1 << 16), (uint32_t)h2 | ((uint32_t)h3 << 16)};
        uint2 lw = {(uint32_t)l0 | ((uint32_t)l1 << 16), (uint32_t)l2 | ((uint32_t)l3 << 16)};
        reinterpret_cast<uint2*>(g_Ah)[idx4] = hw;
        reinterpret_cast<uint2*>(g_Al)[idx4] = lw;
        return;
    }

    const float* src;
    __half *dh, *dl;
    int K, N, tt, ktiles;
    if (bid < 676)       { src = W0; dh = g_W0h; dl = g_W0l; K = INSZ; N = HV;  tt = bid;        ktiles = 26; }
    else if (bid < 1352) { src = W1; dh = g_W1h; dl = g_W1l; K = HV;   N = HV;  tt = bid - 676;  ktiles = 26; }
    else if (bid < 2028) { src = W2; dh = g_W2h; dl = g_W2l; K = HV;   N = HV;  tt = bid - 1352; ktiles = 26; }
    else                 { src = W3; dh = g_W3h; dl = g_W3l; K = HV;   N = DIMV; tt = bid - 2028; ktiles = 26; }
    int kt = tt % ktiles, nt = tt / ktiles;
    int k0 = kt * 64, n0 = nt * 64;

    __shared__ float tile[64][65];
    #pragma unroll
    for (int l = 0; l < 8; l++) {
        int idx = tid + l * 256;
        int kr = idx >> 5, cp = idx & 31;
        int k = k0 + kr, n = n0 + cp * 2;
        float2 v = {0.f, 0.f};
        if (k < K) {
            if (n + 1 < N) v = *reinterpret_cast<const float2*>(src + (size_t)k * N + n);
            else if (n < N) v.x = src[(size_t)k * N + n];
        }
        tile[kr][cp * 2] = v.x;
        tile[kr][cp * 2 + 1] = v.y;
    }
    __syncthreads();
    #pragma unroll
    for (int l = 0; l < 8; l++) {
        int idx = tid + l * 256;
        int n = idx >> 5, kq = idx & 31;
        float x0 = tile[kq * 2][n], x1 = tile[kq * 2 + 1][n];
        unsigned short h0, l0, h1, l1;
        split_h(x0, h0, l0); split_h(x1, h1, l1);
        size_t o = (size_t)(n0 + n) * HP + k0 + kq * 2;
        *reinterpret_cast<uint32_t*>(dh + o) = (uint32_t)h0 | ((uint32_t)h1 << 16);
        *reinterpret_cast<uint32_t*>(dl + o) = (uint32_t)l0 | ((uint32_t)l1 << 16);
    }
}

// ------------------------------------------------------------------
// GEMM core: acc += A[M,K]fp16 @ (Bh+Bl)[N,K]^T, 64x128 CTA tile,
// 3-stage cp.async, 8 warps (2x4), warp tile 32x32, 2 MMA passes.
// ------------------------------------------------------------------
__device__ __forceinline__ void gemm_core(
    uint32_t smbase, const __half* __restrict__ A, int lda,
    const __half* __restrict__ Bh, const __half* __restrict__ Bl, int ldb,
    int m0, int n0, int Kc, float (&acc)[2][4][4]) {

    int tid = threadIdx.x, lane = tid & 31, wid = tid >> 5;
    int wm = wid >> 2, wn = wid & 3;
    int arow = tid >> 2, ach = tid & 3;

    auto load_stage = [&](int buf, int c) {
        uint32_t s = smbase + buf * STG;
        CP_ASYNC16(s + arow * 80 + ach * 16,
                   A + (size_t)(m0 + arow) * lda + c * BK + ach * 8);
        #pragma unroll
        for (int i = 0; i < 2; i++) {
            int f = tid + i * 256;
            int brow = f >> 2, bch = f & 3;
            size_t go = (size_t)(n0 + brow) * ldb + c * BK + bch * 8;
            CP_ASYNC16(s + ST_A + brow * 80 + bch * 16, Bh + go);
            CP_ASYNC16(s + ST_A + ST_B + brow * 80 + bch * 16, Bl + go);
        }
    };

    #pragma unroll
    for (int s = 0; s < NS; s++) { load_stage(s, s); CP_COMMIT(); }

    int a_r = lane & 15, a_c = (lane >> 4) << 3;
    int b_r = (lane & 7) + ((lane >> 4) << 3), b_c = ((lane >> 3) & 1) << 3;

    for (int c = 0; c < Kc; c++) {
        CP_WAIT2();
        __syncthreads();
        uint32_t s = smbase + (c % NS) * STG;

        #pragma unroll
        for (int kk2 = 0; kk2 < 2; kk2++) {
            uint32_t af[2][4], bhf[2][4], blf[2][4];
            #pragma unroll
            for (int mi = 0; mi < 2; mi++) {
                uint32_t off = s + (uint32_t)((wm * 32 + mi * 16 + a_r) * 80 + kk2 * 32 + a_c * 2);
                LDSM4(af[mi], off);
            }
            #pragma unroll
            for (int ni = 0; ni < 2; ni++) {
                uint32_t off = s + ST_A + (uint32_t)((wn * 32 + ni * 16 + b_r) * 80 + kk2 * 32 + b_c * 2);
                LDSM4(bhf[ni], off);
                LDSM4(blf[ni], off + ST_B);
            }
            #pragma unroll
            for (int mi = 0; mi < 2; mi++)
                #pragma unroll
                for (int nj = 0; nj < 4; nj++) {
                    uint32_t* bh = &bhf[nj >> 1][(nj & 1) * 2];
                    uint32_t* bl = &blf[nj >> 1][(nj & 1) * 2];
                    MMA16816(acc[mi][nj], af[mi], bh[0], bh[1]);
                    MMA16816(acc[mi][nj], af[mi], bl[0], bl[1]);
                }
        }
        __syncthreads();
        if (c + NS < Kc) load_stage(c % NS, c + NS);
        CP_COMMIT();
    }
}

// ------------------------------------------------------------------
// hidden layer: C = fp16(tanh(A @ W^T + bias)), full K = HP
// ------------------------------------------------------------------
__global__ __launch_bounds__(256)
void hidden_gemm(const __half* __restrict__ A,
                 const __half* __restrict__ Bh, const __half* __restrict__ Bl,
                 const float* __restrict__ bias, __half* __restrict__ C) {
    extern __shared__ __align__(16) char smraw[];
    uint32_t smbase = smem_u32(smraw);
    int tid = threadIdx.x, lane = tid & 31, wid = tid >> 5;
    int wm = wid >> 2, wn = wid & 3;
    int m0 = blockIdx.y * BM, n0 = blockIdx.x * BN;

    float acc[2][4][4];
    #pragma unroll
    for (int i = 0; i < 2; i++)
        #pragma unroll
        for (int j = 0; j < 4; j++)
            #pragma unroll
            for (int q = 0; q < 4; q++) acc[i][j][q] = 0.f;

    gemm_core(smbase, A, HP, Bh, Bl, HP, m0, n0, HP / BK, acc);

    #pragma unroll
    for (int mi = 0; mi < 2; mi++)
        #pragma unroll
        for (int nj = 0; nj < 4; nj++) {
            float* d = acc[mi][nj];
            int row = m0 + wm * 32 + mi * 16 + (lane >> 2);
            int col = n0 + wn * 32 + nj * 8 + (lane & 3) * 2;
            float bb0 = (col < HV) ? bias[col] : 0.f;
            float bb1 = (col + 1 < HV) ? bias[col + 1] : 0.f;
            float v0 = tanhf(d[0] + bb0), v1 = tanhf(d[1] + bb1);
            float v2 = tanhf(d[2] + bb0), v3 = tanhf(d[3] + bb1);
            *reinterpret_cast<uint32_t*>(C + (size_t)row * HP + col) =
                (uint32_t)h_bits(v0) | ((uint32_t)h_bits(v1) << 16);
            *reinterpret_cast<uint32_t*>(C + (size_t)(row + 8) * HP + col) =
                (uint32_t)h_bits(v2) | ((uint32_t)h_bits(v3) << 16);
        }
}

// ------------------------------------------------------------------
// fused tail: blocks [0,128) = L3 split-K4 partials; [128,192) = forcesum
// ------------------------------------------------------------------
__global__ __launch_bounds__(256)
void tail_gemm(const __half* __restrict__ h2) {
    extern __shared__ __align__(16) char smraw[];
    uint32_t smbase = smem_u32(smraw);
    int b = blockIdx.x;
    int tid = threadIdx.x, lane = tid & 31, wid = tid >> 5;
    int wm = wid >> 2, wn = wid & 3;

    const __half *A, *Bh, *Bl;
    float* out;
    int lda, ldb, ldc, m0, n0, Kc;
    if (b < 128) {
        int sp = b >> 5, r = b & 31;
        m0 = (r >> 2) * BM; n0 = (r & 3) * BN;
        A = h2 + sp * 416;  lda = HP;
        Bh = g_W3h + sp * 416; Bl = g_W3l + sp * 416; ldb = HP;
        Kc = 13; out = g_part + (size_t)sp * BATCH * DIMV; ldc = DIMV;
    } else {
        int r = b - 128;
        m0 = (r >> 2) * BM; n0 = (r & 3) * BN;
        A = g_SCh; lda = DIMV;
        Bh = g_Ah; Bl = g_Al; ldb = DIMV;
        Kc = 16; out = g_FS; ldc = DIMV;
    }

    float acc[2][4][4];
    #pragma unroll
    for (int i = 0; i < 2; i++)
        #pragma unroll
        for (int j = 0; j < 4; j++)
            #pragma unroll
            for (int q = 0; q < 4; q++) acc[i][j][q] = 0.f;

    gemm_core(smbase, A, lda, Bh, Bl, ldb, m0, n0, Kc, acc);

    #pragma unroll
    for (int mi = 0; mi < 2; mi++)
        #pragma unroll
        for (int nj = 0; nj < 4; nj++) {
            float* d = acc[mi][nj];
            int row = m0 + wm * 32 + mi * 16 + (lane >> 2);
            int col = n0 + wn * 32 + nj * 8 + (lane & 3) * 2;
            float2 u0 = {d[0], d[1]}, u1 = {d[2], d[3]};
            *reinterpret_cast<float2*>(out + (size_t)row * ldc + col) = u0;
            *reinterpret_cast<float2*>(out + (size_t)(row + 8) * ldc + col) = u1;
        }
}

// ------------------------------------------------------------------
// final: cf = sum parts + b3; force = cf*(cos*FSs - sin*FSc)/dim + freqs;
// f1 = rowsum(cf^2)
// ------------------------------------------------------------------
__global__ __launch_bounds__(256)
void final_kernel(const float* __restrict__ freqs, const float* __restrict__ b3,
                  float* __restrict__ out) {
    int b = blockIdx.x, tid = threadIdx.x;
    float sum = 0.f;
    for (int i = tid; i < DIMV; i += 256) {
        size_t o = (size_t)b * DIMV + i;
        float cf = g_part[o] + g_part[BATCH * DIMV + o] + g_part[2 * BATCH * DIMV + o]
                 + g_part[3 * BATCH * DIMV + o] + b3[i];
        float s = g_SC[o];
        float c = g_SC[BATCH * DIMV + o];
        float fs = c * g_FS[o] - s * g_FS[BATCH * DIMV + o];
        out[b * (DIMV + 1) + i] = cf * fs * (1.0f / DIMV) + freqs[o];
        sum += cf * cf;
    }
    __shared__ float red[8];
    #pragma unroll
    for (int o = 16; o; o >>= 1) sum += __shfl_down_sync(0xffffffffu, sum, o);
    if ((tid & 31) == 0) red[tid >> 5] = sum;
    __syncthreads();
    if (tid < 8) {
        float v = red[tid];
        #pragma unroll
        for (int o = 4; o; o >>= 1) v += __shfl_down_sync(0xffu, v, o);
        if (tid == 0) out[b * (DIMV + 1) + DIMV] = v;
    }
}

// ------------------------------------------------------------------
// launch
// ------------------------------------------------------------------
extern "C" void kernel_launch(void* const* d_in, const int* in_sizes, int n_in,
                              void* d_out, int out_size) {
    const float* t     = (const float*)d_in[0];
    const float* y     = (const float*)d_in[1];
    const float* freqs = (const float*)d_in[2];
    const float* A     = (const float*)d_in[3];
    const float* W0    = (const float*)d_in[4];
    const float* b0    = (const float*)d_in[5];
    const float* W1    = (const float*)d_in[6];
    const float* b1    = (const float*)d_in[7];
    const float* W2    = (const float*)d_in[8];
    const float* b2    = (const float*)d_in[9];
    const float* W3    = (const float*)d_in[10];
    const float* b3    = (const float*)d_in[11];
    float* out = (float*)d_out;

    __half *p_a0, *p_hA, *p_hB;
    __half *p_W0h, *p_W0l, *p_W1h, *p_W1l, *p_W2h, *p_W2l;
    cudaGetSymbolAddress((void**)&p_a0, g_a0);
    cudaGetSymbolAddress((void**)&p_hA, g_hA);
    cudaGetSymbolAddress((void**)&p_hB, g_hB);
    cudaGetSymbolAddress((void**)&p_W0h, g_W0h); cudaGetSymbolAddress((void**)&p_W0l, g_W0l);
    cudaGetSymbolAddress((void**)&p_W1h, g_W1h); cudaGetSymbolAddress((void**)&p_W1l, g_W1l);
    cudaGetSymbolAddress((void**)&p_W2h, g_W2h); cudaGetSymbolAddress((void**)&p_W2l, g_W2l);

    cudaFuncSetAttribute(hidden_gemm, cudaFuncAttributeMaxDynamicSharedMemorySize, SMEM_TOT);
    cudaFuncSetAttribute(tail_gemm,   cudaFuncAttributeMaxDynamicSharedMemorySize, SMEM_TOT);

    prep_kernel<<<BATCH, 256>>>(t, y, freqs);
    convert_all<<<2492, 256>>>(W0, W1, W2, W3, A);

    dim3 gridH(HP / BN, BATCH / BM);   // (13, 8) = 104 CTAs
    hidden_gemm<<<gridH, 256, SMEM_TOT>>>(p_a0, p_W0h, p_W0l, b0, p_hA);
    hidden_gemm<<<gridH, 256, SMEM_TOT>>>(p_hA, p_W1h, p_W1l, b1, p_hB);
    hidden_gemm<<<gridH, 256, SMEM_TOT>>>(p_hB, p_W2h, p_W2l, b2, p_hA);

    tail_gemm<<<192, 256, SMEM_TOT>>>(p_hA);

    final_kernel<<<BATCH, 256>>>(freqs, b3, out);
}

// round 5
// speedup vs baseline: 6.4334x; 1.5712x over previous
#include <cuda_runtime.h>
#include <cuda_fp16.h>
#include <math.h>
#include <stdint.h>

#define BATCH 512
#define DIMV  512
#define INSZ  1537
#define HV    1538
#define HP    1664          // padded h / in_sz (multiple of 128)

// GEMM tiling
#define BM 64
#define BN 128
#define BK 32
#define NS 4                      // cp.async stages
#define ST_A (64 * 80)            // 5120
#define ST_B (128 * 80)           // 10240
#define STG  (ST_A + ST_B)        // 15360 : A | B
#define SMEM_TOT (NS * STG)       // 61440 -> 2 CTAs/SM

// ------------------------------------------------------------------
// scratch (__device__ globals; no allocations allowed)
// ------------------------------------------------------------------
__device__ __half g_a0[BATCH * HP];
__device__ __half g_hA[BATCH * HP];
__device__ __half g_hB[BATCH * HP];
__device__ float  g_p0[BATCH * HP];            // split-K partials
__device__ float  g_p1[BATCH * HP];
__device__ __half g_SCh[2 * BATCH * DIMV];     // fp16 [sin; cos]
__device__ float  g_SC[2 * BATCH * DIMV];      // fp32 [sin; cos]
__device__ float  g_FS[2 * BATCH * DIMV];      // forcesum GEMM out
__device__ float  g_part[4 * BATCH * DIMV];    // W3 split-K partials

__device__ __half g_W0[HP * HP];
__device__ __half g_W1[HP * HP];
__device__ __half g_W2[HP * HP];
__device__ __half g_W3[DIMV * HP];
__device__ __half g_A[DIMV * DIMV];

// ------------------------------------------------------------------
// helpers
// ------------------------------------------------------------------
__device__ __forceinline__ uint32_t smem_u32(const void* p) {
    uint32_t a;
    asm("{ .reg .u64 t; cvta.to.shared.u64 t, %1; cvt.u32.u64 %0, t; }"
        : "=r"(a) : "l"(p));
    return a;
}

#define CP_ASYNC16(dst, src) \
    asm volatile("cp.async.cg.shared.global [%0], [%1], 16;" \
                 :: "r"(dst), "l"(src) : "memory")
#define CP_COMMIT() asm volatile("cp.async.commit_group;" ::: "memory")
#define CP_WAIT()   asm volatile("cp.async.wait_group %0;" :: "n"(NS - 1) : "memory")

#define LDSM4(r, addr) \
    asm volatile("ldmatrix.sync.aligned.m8n8.x4.shared.b16 {%0,%1,%2,%3}, [%4];" \
                 : "=r"((r)[0]), "=r"((r)[1]), "=r"((r)[2]), "=r"((r)[3]) : "r"(addr))

#define MMA16816(d, a, b0, b1) \
    asm volatile("mma.sync.aligned.m16n8k16.row.col.f32.f16.f16.f32 " \
                 "{%0,%1,%2,%3}, {%4,%5,%6,%7}, {%8,%9}, {%0,%1,%2,%3};" \
                 : "+f"((d)[0]), "+f"((d)[1]), "+f"((d)[2]), "+f"((d)[3]) \
                 : "r"((a)[0]), "r"((a)[1]), "r"((a)[2]), "r"((a)[3]), \
                   "r"(b0), "r"(b1))

// ------------------------------------------------------------------
// prep: a0 = fp16[cos, sin, t-1, freqs, 0pad]; SC fp16+fp32 [sin; cos]
// ------------------------------------------------------------------
__global__ void prep_kernel(const float* __restrict__ t, const float* __restrict__ y,
                            const float* __restrict__ freqs) {
    int b = blockIdx.x, tid = threadIdx.x;
    float temb = t[0] - 1.0f;
    __half* row = g_a0 + (size_t)b * HP;
    for (int i = tid; i < DIMV; i += 256) {
        float yv = y[b * (DIMV + 1) + i];
        float s, c;
        sincosf(yv, &s, &c);
        float fq = freqs[b * DIMV + i];
        row[i] = __float2half_rn(c);
        row[DIMV + i] = __float2half_rn(s);
        row[2 * DIMV + 1 + i] = __float2half_rn(fq);
        g_SC[b * DIMV + i] = s;
        g_SC[(BATCH + b) * DIMV + i] = c;
        g_SCh[b * DIMV + i] = __float2half_rn(s);
        g_SCh[(BATCH + b) * DIMV + i] = __float2half_rn(c);
    }
    if (tid == 0) row[2 * DIMV] = __float2half_rn(temb);
    for (int i = INSZ + tid; i < HP; i += 256) row[i] = __ushort_as_half(0);
}

// ------------------------------------------------------------------
// fused conversion: W0..W3 transpose+fp16 (64x64 tiles) + A fp16
// block dispatch: [0,676) W0 | [676,1352) W1 | [1352,2028) W2 |
//                 [2028,2236) W3 | [2236,2492) A elementwise
// ------------------------------------------------------------------
__global__ __launch_bounds__(256)
void convert_all(const float* __restrict__ W0, const float* __restrict__ W1,
                 const float* __restrict__ W2, const float* __restrict__ W3,
                 const float* __restrict__ A) {
    int bid = blockIdx.x, tid = threadIdx.x;

    if (bid >= 2236) {               // A: elementwise fp16, float4 vectorized
        int idx4 = (bid - 2236) * 256 + tid;
        float4 v = reinterpret_cast<const float4*>(A)[idx4];
        __half2 h0 = {__float2half_rn(v.x), __float2half_rn(v.y)};
        __half2 h1 = {__float2half_rn(v.z), __float2half_rn(v.w)};
        uint2 w = {*(uint32_t*)&h0, *(uint32_t*)&h1};
        reinterpret_cast<uint2*>(g_A)[idx4] = w;
        return;
    }

    const float* src;
    __half* dh;
    int K, N, tt;
    if (bid < 676)       { src = W0; dh = g_W0; K = INSZ; N = HV;   tt = bid;        }
    else if (bid < 1352) { src = W1; dh = g_W1; K = HV;   N = HV;   tt = bid - 676;  }
    else if (bid < 2028) { src = W2; dh = g_W2; K = HV;   N = HV;   tt = bid - 1352; }
    else                 { src = W3; dh = g_W3; K = HV;   N = DIMV; tt = bid - 2028; }
    int kt = tt % 26, nt = tt / 26;
    int k0 = kt * 64, n0 = nt * 64;

    __shared__ float tile[64][65];
    #pragma unroll
    for (int l = 0; l < 8; l++) {
        int idx = tid + l * 256;
        int kr = idx >> 5, cp = idx & 31;
        int k = k0 + kr, n = n0 + cp * 2;
        float2 v = {0.f, 0.f};
        if (k < K) {
            if (n + 1 < N) v = *reinterpret_cast<const float2*>(src + (size_t)k * N + n);
            else if (n < N) v.x = src[(size_t)k * N + n];
        }
        tile[kr][cp * 2] = v.x;
        tile[kr][cp * 2 + 1] = v.y;
    }
    __syncthreads();
    #pragma unroll
    for (int l = 0; l < 8; l++) {
        int idx = tid + l * 256;
        int n = idx >> 5, kq = idx & 31;
        __half2 h = {__float2half_rn(tile[kq * 2][n]), __float2half_rn(tile[kq * 2 + 1][n])};
        size_t o = (size_t)(n0 + n) * HP + k0 + kq * 2;
        *reinterpret_cast<uint32_t*>(dh + o) = *(uint32_t*)&h;
    }
}

// ------------------------------------------------------------------
// GEMM core: acc += A[M,K]fp16 @ B[N,K]^T fp16, 64x128 CTA tile,
// NS-stage cp.async, 8 warps (2x4), warp tile 32x32, single MMA pass.
// ------------------------------------------------------------------
__device__ __forceinline__ void gemm_core(
    uint32_t smbase, const __half* __restrict__ A, int lda,
    const __half* __restrict__ B, int ldb,
    int m0, int n0, int Kc, float (&acc)[2][4][4]) {

    int tid = threadIdx.x, lane = tid & 31, wid = tid >> 5;
    int wm = wid >> 2, wn = wid & 3;
    int arow = tid >> 2, ach = tid & 3;

    auto load_stage = [&](int buf, int c) {
        uint32_t s = smbase + buf * STG;
        CP_ASYNC16(s + arow * 80 + ach * 16,
                   A + (size_t)(m0 + arow) * lda + c * BK + ach * 8);
        #pragma unroll
        for (int i = 0; i < 2; i++) {
            int f = tid + i * 256;
            int brow = f >> 2, bch = f & 3;
            CP_ASYNC16(s + ST_A + brow * 80 + bch * 16,
                       B + (size_t)(n0 + brow) * ldb + c * BK + bch * 8);
        }
    };

    #pragma unroll
    for (int s = 0; s < NS; s++) { load_stage(s, s); CP_COMMIT(); }

    int a_r = lane & 15, a_c = (lane >> 4) << 3;
    int b_r = (lane & 7) + ((lane >> 4) << 3), b_c = ((lane >> 3) & 1) << 3;

    for (int c = 0; c < Kc; c++) {
        CP_WAIT();
        __syncthreads();
        uint32_t s = smbase + (c % NS) * STG;

        #pragma unroll
        for (int kk2 = 0; kk2 < 2; kk2++) {
            uint32_t af[2][4], bf[2][4];
            #pragma unroll
            for (int mi = 0; mi < 2; mi++) {
                uint32_t off = s + (uint32_t)((wm * 32 + mi * 16 + a_r) * 80 + kk2 * 32 + a_c * 2);
                LDSM4(af[mi], off);
            }
            #pragma unroll
            for (int ni = 0; ni < 2; ni++) {
                uint32_t off = s + ST_A + (uint32_t)((wn * 32 + ni * 16 + b_r) * 80 + kk2 * 32 + b_c * 2);
                LDSM4(bf[ni], off);
            }
            #pragma unroll
            for (int mi = 0; mi < 2; mi++)
                #pragma unroll
                for (int nj = 0; nj < 4; nj++) {
                    uint32_t* bb = &bf[nj >> 1][(nj & 1) * 2];
                    MMA16816(acc[mi][nj], af[mi], bb[0], bb[1]);
                }
        }
        __syncthreads();
        if (c + NS < Kc) load_stage(c % NS, c + NS);
        CP_COMMIT();
    }
}

// ------------------------------------------------------------------
// hidden layer GEMM: split-K2, fp32 partials (z = split index)
// ------------------------------------------------------------------
__global__ __launch_bounds__(256)
void hidden_gemm(const __half* __restrict__ A, const __half* __restrict__ B) {
    extern __shared__ __align__(16) char smraw[];
    uint32_t smbase = smem_u32(smraw);
    int tid = threadIdx.x, lane = tid & 31, wid = tid >> 5;
    int wm = wid >> 2, wn = wid & 3;
    int m0 = blockIdx.y * BM, n0 = blockIdx.x * BN;
    int sp = blockIdx.z;
    float* out = sp ? g_p1 : g_p0;

    float acc[2][4][4];
    #pragma unroll
    for (int i = 0; i < 2; i++)
        #pragma unroll
        for (int j = 0; j < 4; j++)
            #pragma unroll
            for (int q = 0; q < 4; q++) acc[i][j][q] = 0.f;

    gemm_core(smbase, A + sp * 832, HP, B + sp * 832, HP, m0, n0, 832 / BK, acc);

    #pragma unroll
    for (int mi = 0; mi < 2; mi++)
        #pragma unroll
        for (int nj = 0; nj < 4; nj++) {
            float* d = acc[mi][nj];
            int row = m0 + wm * 32 + mi * 16 + (lane >> 2);
            int col = n0 + wn * 32 + nj * 8 + (lane & 3) * 2;
            float2 u0 = {d[0], d[1]}, u1 = {d[2], d[3]};
            *reinterpret_cast<float2*>(out + (size_t)row * HP + col) = u0;
            *reinterpret_cast<float2*>(out + (size_t)(row + 8) * HP + col) = u1;
        }
}

// ------------------------------------------------------------------
// combine: C = fp16(tanh(p0 + p1 + bias)), vector-4
// ------------------------------------------------------------------
__global__ __launch_bounds__(256)
void combine_kernel(const float* __restrict__ bias, __half* __restrict__ C) {
    int idx4 = blockIdx.x * 256 + threadIdx.x;        // 832 blocks
    int col = (idx4 * 4) % HP;
    float4 a = reinterpret_cast<const float4*>(g_p0)[idx4];
    float4 b = reinterpret_cast<const float4*>(g_p1)[idx4];
    float v[4] = {a.x + b.x, a.y + b.y, a.z + b.z, a.w + b.w};
    #pragma unroll
    for (int i = 0; i < 4; i++) {
        float bb = (col + i < HV) ? bias[col + i] : 0.f;
        v[i] = tanhf(v[i] + bb);
    }
    __half2 h0 = {__float2half_rn(v[0]), __float2half_rn(v[1])};
    __half2 h1 = {__float2half_rn(v[2]), __float2half_rn(v[3])};
    uint2 w = {*(uint32_t*)&h0, *(uint32_t*)&h1};
    reinterpret_cast<uint2*>(C)[idx4] = w;
}

// ------------------------------------------------------------------
// fused tail: blocks [0,128) = W3 split-K4 partials; [128,192) = forcesum
// ------------------------------------------------------------------
__global__ __launch_bounds__(256)
void tail_gemm(const __half* __restrict__ h2) {
    extern __shared__ __align__(16) char smraw[];
    uint32_t smbase = smem_u32(smraw);
    int b = blockIdx.x;
    int tid = threadIdx.x, lane = tid & 31, wid = tid >> 5;
    int wm = wid >> 2, wn = wid & 3;

    const __half *A, *B;
    float* out;
    int lda, ldb, ldc, m0, n0, Kc;
    if (b < 128) {
        int sp = b >> 5, r = b & 31;
        m0 = (r >> 2) * BM; n0 = (r & 3) * BN;
        A = h2 + sp * 416;  lda = HP;
        B = g_W3 + sp * 416; ldb = HP;
        Kc = 13; out = g_part + (size_t)sp * BATCH * DIMV; ldc = DIMV;
    } else {
        int r = b - 128;
        m0 = (r >> 2) * BM; n0 = (r & 3) * BN;
        A = g_SCh; lda = DIMV;
        B = g_A; ldb = DIMV;
        Kc = 16; out = g_FS; ldc = DIMV;
    }

    float acc[2][4][4];
    #pragma unroll
    for (int i = 0; i < 2; i++)
        #pragma unroll
        for (int j = 0; j < 4; j++)
            #pragma unroll
            for (int q = 0; q < 4; q++) acc[i][j][q] = 0.f;

    gemm_core(smbase, A, lda, B, ldb, m0, n0, Kc, acc);

    #pragma unroll
    for (int mi = 0; mi < 2; mi++)
        #pragma unroll
        for (int nj = 0; nj < 4; nj++) {
            float* d = acc[mi][nj];
            int row = m0 + wm * 32 + mi * 16 + (lane >> 2);
            int col = n0 + wn * 32 + nj * 8 + (lane & 3) * 2;
            float2 u0 = {d[0], d[1]}, u1 = {d[2], d[3]};
            *reinterpret_cast<float2*>(out + (size_t)row * ldc + col) = u0;
            *reinterpret_cast<float2*>(out + (size_t)(row + 8) * ldc + col) = u1;
        }
}

// ------------------------------------------------------------------
// final: cf = sum parts + b3; force = cf*(cos*FSs - sin*FSc)/dim + freqs;
// f1 = rowsum(cf^2)
// ------------------------------------------------------------------
__global__ __launch_bounds__(256)
void final_kernel(const float* __restrict__ freqs, const float* __restrict__ b3,
                  float* __restrict__ out) {
    int b = blockIdx.x, tid = threadIdx.x;
    float sum = 0.f;
    for (int i = tid; i < DIMV; i += 256) {
        size_t o = (size_t)b * DIMV + i;
        float cf = g_part[o] + g_part[BATCH * DIMV + o] + g_part[2 * BATCH * DIMV + o]
                 + g_part[3 * BATCH * DIMV + o] + b3[i];
        float s = g_SC[o];
        float c = g_SC[BATCH * DIMV + o];
        float fs = c * g_FS[o] - s * g_FS[BATCH * DIMV + o];
        out[b * (DIMV + 1) + i] = cf * fs * (1.0f / DIMV) + freqs[o];
        sum += cf * cf;
    }
    __shared__ float red[8];
    #pragma unroll
    for (int o = 16; o; o >>= 1) sum += __shfl_down_sync(0xffffffffu, sum, o);
    if ((tid & 31) == 0) red[tid >> 5] = sum;
    __syncthreads();
    if (tid < 8) {
        float v = red[tid];
        #pragma unroll
        for (int o = 4; o; o >>= 1) v += __shfl_down_sync(0xffu, v, o);
        if (tid == 0) out[b * (DIMV + 1) + DIMV] = v;
    }
}

// ------------------------------------------------------------------
// launch
// ------------------------------------------------------------------
extern "C" void kernel_launch(void* const* d_in, const int* in_sizes, int n_in,
                              void* d_out, int out_size) {
    const float* t     = (const float*)d_in[0];
    const float* y     = (const float*)d_in[1];
    const float* freqs = (const float*)d_in[2];
    const float* A     = (const float*)d_in[3];
    const float* W0    = (const float*)d_in[4];
    const float* b0    = (const float*)d_in[5];
    const float* W1    = (const float*)d_in[6];
    const float* b1    = (const float*)d_in[7];
    const float* W2    = (const float*)d_in[8];
    const float* b2    = (const float*)d_in[9];
    const float* W3    = (const float*)d_in[10];
    const float* b3    = (const float*)d_in[11];
    float* out = (float*)d_out;

    __half *p_a0, *p_hA, *p_hB, *p_W0, *p_W1, *p_W2;
    cudaGetSymbolAddress((void**)&p_a0, g_a0);
    cudaGetSymbolAddress((void**)&p_hA, g_hA);
    cudaGetSymbolAddress((void**)&p_hB, g_hB);
    cudaGetSymbolAddress((void**)&p_W0, g_W0);
    cudaGetSymbolAddress((void**)&p_W1, g_W1);
    cudaGetSymbolAddress((void**)&p_W2, g_W2);

    cudaFuncSetAttribute(hidden_gemm, cudaFuncAttributeMaxDynamicSharedMemorySize, SMEM_TOT);
    cudaFuncSetAttribute(tail_gemm,   cudaFuncAttributeMaxDynamicSharedMemorySize, SMEM_TOT);

    prep_kernel<<<BATCH, 256>>>(t, y, freqs);
    convert_all<<<2492, 256>>>(W0, W1, W2, W3, A);

    dim3 gridH(HP / BN, BATCH / BM, 2);   // (13, 8, 2) = 208 CTAs
    hidden_gemm<<<gridH, 256, SMEM_TOT>>>(p_a0, p_W0);
    combine_kernel<<<832, 256>>>(b0, p_hA);
    hidden_gemm<<<gridH, 256, SMEM_TOT>>>(p_hA, p_W1);
    combine_kernel<<<832, 256>>>(b1, p_hB);
    hidden_gemm<<<gridH, 256, SMEM_TOT>>>(p_hB, p_W2);
    combine_kernel<<<832, 256>>>(b2, p_hA);

    tail_gemm<<<192, 256, SMEM_TOT>>>(p_hA);

    final_kernel<<<BATCH, 256>>>(freqs, b3, out);
}